// round 3
// baseline (speedup 1.0000x reference)
#include <cuda_runtime.h>

// ----------------------------------------------------------------------------
// Ops_GetPointFeat_spconv: multi-scale 3-NN inverse-distance interpolation.
//
// Scales: s = {2,4,8,16}; M = {16000,4000,512,64}; C = {32,64,128,256}.
// center = idx[1..3] * (0.015*s) + OFFSET + 0.5*(0.015*s),
//   OFFSET = (-0.5*0.015)*64 = -0.48 (computed in the same fp32 order as numpy).
// For each of 8192 points: 3 nearest centers by squared distance
// (ties -> lower voxel index, matching jax.lax.top_k), weights = (1/(d+1e-8))
// normalized, output = weighted sum of feature rows, concatenated to [8192,480].
// ----------------------------------------------------------------------------

#define N_POINTS      8192
#define TOTAL_CENTERS 20576   // 16000 + 4000 + 512 + 64
#define PTS_PER_BLK   32
#define K_SPLIT       4
#define BLK_THREADS   (PTS_PER_BLK * K_SPLIT)   // 128
#define OUT_STRIDE    480

static __device__ float4 g_centers[TOTAL_CENTERS];

// ---------------------------------------------------------------------------
// Kernel 1: voxel index -> metric center, all scales in one launch.
// ---------------------------------------------------------------------------
__global__ void centers_kernel(const int* __restrict__ i1, const int* __restrict__ i2,
                               const int* __restrict__ i3, const int* __restrict__ i4)
{
    int i = blockIdx.x * blockDim.x + threadIdx.x;
    if (i >= TOTAL_CENTERS) return;

    const int* idx; int local; float s;
    if (i < 16000)      { idx = i1; local = i;         s = 2.0f;  }
    else if (i < 20000) { idx = i2; local = i - 16000; s = 4.0f;  }
    else if (i < 20512) { idx = i3; local = i - 20000; s = 8.0f;  }
    else                { idx = i4; local = i - 20512; s = 16.0f; }

    // Match numpy/jax fp32 op order exactly (no contraction).
    float ve   = __fmul_rn(0.015f, s);                          // UNIT * s
    float off  = __fmul_rn(__fmul_rn(-0.5f, 0.015f), 64.0f);    // OFFSET
    float half = __fmul_rn(0.5f, ve);                           // 0.5 * voxel_extent

    int ix = idx[local * 4 + 1];
    int iy = idx[local * 4 + 2];
    int iz = idx[local * 4 + 3];

    float4 c;
    c.x = __fadd_rn(__fadd_rn(__fmul_rn((float)ix, ve), off), half);
    c.y = __fadd_rn(__fadd_rn(__fmul_rn((float)iy, ve), off), half);
    c.z = __fadd_rn(__fadd_rn(__fmul_rn((float)iz, ve), off), half);
    c.w = 0.0f;
    g_centers[i] = c;
}

// ---------------------------------------------------------------------------
// Kernel 2: per (point-tile, scale) CTA. K_SPLIT threads per point scan
// disjoint index stripes keeping a register top-3, then merge in smem with
// (d2, index) lexicographic order, then cooperative feature gather.
// ---------------------------------------------------------------------------
__global__ void __launch_bounds__(BLK_THREADS)
interp_kernel(const float* __restrict__ points,
              const float* __restrict__ f1, const float* __restrict__ f2,
              const float* __restrict__ f3, const float* __restrict__ f4,
              float* __restrict__ out)
{
    int M, C, cOff, oOff;
    const float* feats;
    switch (blockIdx.y) {
        case 0:  M = 16000; C = 32;  cOff = 0;     oOff = 0;   feats = f1; break;
        case 1:  M = 4000;  C = 64;  cOff = 16000; oOff = 32;  feats = f2; break;
        case 2:  M = 512;   C = 128; cOff = 20000; oOff = 96;  feats = f3; break;
        default: M = 64;    C = 256; cOff = 20512; oOff = 224; feats = f4; break;
    }
    const float4* __restrict__ ctr = g_centers + cOff;

    const int t = threadIdx.x;
    const int k = t & (K_SPLIT - 1);
    const int p = t >> 2;                       // local point 0..31
    const int pg = blockIdx.x * PTS_PER_BLK + p;

    const float px = points[pg * 3 + 0];
    const float py = points[pg * 3 + 1];
    const float pz = points[pg * 3 + 2];

    float b0 = 3.0e38f, b1 = 3.0e38f, b2 = 3.0e38f;
    int   i0 = 0x7fffffff, i1 = 0x7fffffff, i2 = 0x7fffffff;

    // Stripe m = k, k+4, k+8, ... ; strict '<' keeps the earliest (lowest-index)
    // candidate on exact ties within the stripe, matching top_k stability.
    #pragma unroll 4
    for (int m = k; m < M; m += K_SPLIT) {
        float4 c = __ldg(&ctr[m]);
        float dx = __fsub_rn(px, c.x);
        float dy = __fsub_rn(py, c.y);
        float dz = __fsub_rn(pz, c.z);
        // ((dx*dx + dy*dy) + dz*dz) with rn ops, no fma — match jax fp order.
        float d = __fadd_rn(__fadd_rn(__fmul_rn(dx, dx), __fmul_rn(dy, dy)),
                            __fmul_rn(dz, dz));
        if (d < b2) {
            if (d < b1) {
                b2 = b1; i2 = i1;
                if (d < b0) { b1 = b0; i1 = i0; b0 = d; i0 = m; }
                else        { b1 = d;  i1 = m; }
            } else { b2 = d; i2 = m; }
        }
    }

    __shared__ float sd[PTS_PER_BLK][3 * K_SPLIT];
    __shared__ int   si[PTS_PER_BLK][3 * K_SPLIT];
    __shared__ float sw[PTS_PER_BLK][3];
    __shared__ int   sn[PTS_PER_BLK][3];

    sd[p][k * 3 + 0] = b0; si[p][k * 3 + 0] = i0;
    sd[p][k * 3 + 1] = b1; si[p][k * 3 + 1] = i1;
    sd[p][k * 3 + 2] = b2; si[p][k * 3 + 2] = i2;
    __syncthreads();

    if (k == 0) {
        float cd[12]; int ci[12];
        #pragma unroll
        for (int j = 0; j < 12; j++) { cd[j] = sd[p][j]; ci[j] = si[p][j]; }

        float bd_[3]; int bi_[3];
        #pragma unroll
        for (int r = 0; r < 3; r++) {
            float bd = cd[0]; int bi = ci[0]; int bj = 0;
            #pragma unroll
            for (int j = 1; j < 12; j++) {
                bool better = (cd[j] < bd) || (cd[j] == bd && ci[j] < bi);
                if (better) { bd = cd[j]; bi = ci[j]; bj = j; }
            }
            cd[bj] = 3.4e38f; ci[bj] = 0x7fffffff;
            bd_[r] = bd; bi_[r] = bi;
        }

        float r0 = __fdiv_rn(1.0f, __fadd_rn(bd_[0], 1e-8f));
        float r1 = __fdiv_rn(1.0f, __fadd_rn(bd_[1], 1e-8f));
        float r2 = __fdiv_rn(1.0f, __fadd_rn(bd_[2], 1e-8f));
        float s  = __fadd_rn(__fadd_rn(r0, r1), r2);
        sw[p][0] = __fdiv_rn(r0, s);
        sw[p][1] = __fdiv_rn(r1, s);
        sw[p][2] = __fdiv_rn(r2, s);
        sn[p][0] = bi_[0]; sn[p][1] = bi_[1]; sn[p][2] = bi_[2];
    }
    __syncthreads();

    // Cooperative gather + weighted sum: PTS_PER_BLK * C output elements.
    const int total = PTS_PER_BLK * C;
    for (int e = t; e < total; e += BLK_THREADS) {
        int pp = e / C;
        int c  = e - pp * C;
        int r0 = sn[pp][0], r1 = sn[pp][1], r2 = sn[pp][2];
        float w0 = sw[pp][0], w1 = sw[pp][1], w2 = sw[pp][2];
        float v = w0 * feats[r0 * C + c];
        v = fmaf(w1, feats[r1 * C + c], v);
        v = fmaf(w2, feats[r2 * C + c], v);
        out[(blockIdx.x * PTS_PER_BLK + pp) * OUT_STRIDE + oOff + c] = v;
    }
}

// ---------------------------------------------------------------------------
extern "C" void kernel_launch(void* const* d_in, const int* in_sizes, int n_in,
                              void* d_out, int out_size)
{
    // All 10 input element counts are distinct — identify by size, order-proof.
    const float* points = nullptr;
    const int*   idx[4]   = {nullptr, nullptr, nullptr, nullptr};
    const float* feats[4] = {nullptr, nullptr, nullptr, nullptr};

    for (int i = 0; i < n_in; i++) {
        switch (in_sizes[i]) {
            case 24576:  points   = (const float*)d_in[i]; break; // points [8192,3]
            case 64000:  idx[0]   = (const int*)  d_in[i]; break; // indices1 [16000,4]
            case 512000: feats[0] = (const float*)d_in[i]; break; // feats1 [16000,32]
            case 16000:  idx[1]   = (const int*)  d_in[i]; break; // indices2 [4000,4]
            case 256000: feats[1] = (const float*)d_in[i]; break; // feats2 [4000,64]
            case 2048:   idx[2]   = (const int*)  d_in[i]; break; // indices3 [512,4]
            case 65536:  feats[2] = (const float*)d_in[i]; break; // feats3 [512,128]
            case 256:    idx[3]   = (const int*)  d_in[i]; break; // indices4 [64,4]
            case 16384:  feats[3] = (const float*)d_in[i]; break; // feats4 [64,256]
            default: break;                                       // batch_ids (8192): unused
        }
    }

    centers_kernel<<<(TOTAL_CENTERS + 255) / 256, 256>>>(idx[0], idx[1], idx[2], idx[3]);

    dim3 grid(N_POINTS / PTS_PER_BLK, 4);   // 256 point-tiles x 4 scales
    interp_kernel<<<grid, BLK_THREADS>>>(points, feats[0], feats[1], feats[2], feats[3],
                                         (float*)d_out);
}

// round 4
// speedup vs baseline: 4.0339x; 4.0339x over previous
#include <cuda_runtime.h>

// ----------------------------------------------------------------------------
// Ops_GetPointFeat_spconv: multi-scale 3-NN inverse-distance interpolation,
// grid-bucketed. Scales s={2,4,8,16}; M={16000,4000,512,64}; C={32,64,128,256}.
//
// Centers sit on regular grids (G = 64/s per axis). We bucket centers by their
// own integer voxel coords, then each point does an expanding-ring search with
// a provably conservative stop bound. Selection = lexicographic (d2, index)
// min  ==  jax.lax.top_k tie-breaking (lower index wins on equal d2), and is
// independent of bucket slot order (atomic scatter order doesn't matter).
// d2 uses the exact RN op order of the reference (no FMA contraction).
// ----------------------------------------------------------------------------

#define N_POINTS   8192
#define OUT_STRIDE 480
#define CAP        32

// cells: 32^3 + 16^3 + 8^3 + 4^3 = 32768 + 4096 + 512 + 64 = 37440
#define NCELLS 37440
#define NSLOTS (NCELLS * CAP)

static __device__ int    g_cnt[NCELLS];
static __device__ float4 g_bctr[NSLOTS];   // bucketed centers
static __device__ int    g_bidx[NSLOTS];   // bucketed feature-row indices

// ---------------------------------------------------------------------------
__global__ void k_zero()
{
    int i = blockIdx.x * 256 + threadIdx.x;
    if (i < NCELLS) g_cnt[i] = 0;
}

// ---------------------------------------------------------------------------
// Scatter all 20576 centers into their cells (center coords computed with the
// exact RN op order of the reference tensor2points).
// ---------------------------------------------------------------------------
__global__ void k_scatter(const int* __restrict__ i1, const int* __restrict__ i2,
                          const int* __restrict__ i3, const int* __restrict__ i4)
{
    int t = blockIdx.x * 256 + threadIdx.x;
    if (t >= 20576) return;

    int s, local, G, cellBase; const int* idx;
    if (t < 16000)      { s = 0; local = t;         G = 32; cellBase = 0;     idx = i1; }
    else if (t < 20000) { s = 1; local = t - 16000; G = 16; cellBase = 32768; idx = i2; }
    else if (t < 20512) { s = 2; local = t - 20000; G = 8;  cellBase = 36864; idx = i3; }
    else                { s = 3; local = t - 20512; G = 4;  cellBase = 37376; idx = i4; }

    int ix = idx[local * 4 + 1];
    int iy = idx[local * 4 + 2];
    int iz = idx[local * 4 + 3];

    float sf   = (float)(2 << s);
    float ve   = __fmul_rn(0.015f, sf);
    float off  = __fmul_rn(__fmul_rn(-0.5f, 0.015f), 64.0f);  // -0.48
    float half = __fmul_rn(0.5f, ve);

    float4 c;
    c.x = __fadd_rn(__fadd_rn(__fmul_rn((float)ix, ve), off), half);
    c.y = __fadd_rn(__fadd_rn(__fmul_rn((float)iy, ve), off), half);
    c.z = __fadd_rn(__fadd_rn(__fmul_rn((float)iz, ve), off), half);
    c.w = 0.0f;

    int cell = cellBase + (ix * G + iy) * G + iz;
    int pos  = atomicAdd(&g_cnt[cell], 1);
    if (pos < CAP) {
        g_bctr[cell * CAP + pos] = c;
        g_bidx[cell * CAP + pos] = local;
    }
}

// ---------------------------------------------------------------------------
// Fused query + gather. CTA = 32 points; warp w handles scale w for all 32
// points (uniform scale per warp). Ring search -> weights in smem -> fused
// cooperative feature gather for the CTA's 32 x 480 outputs.
// ---------------------------------------------------------------------------
__global__ void __launch_bounds__(128)
k_query(const float* __restrict__ pts,
        const float* __restrict__ f1, const float* __restrict__ f2,
        const float* __restrict__ f3, const float* __restrict__ f4,
        float* __restrict__ out)
{
    const int s  = threadIdx.x >> 5;        // scale = warp id
    const int lp = threadIdx.x & 31;        // local point
    const int p  = blockIdx.x * 32 + lp;

    const float px = pts[p * 3 + 0];
    const float py = pts[p * 3 + 1];
    const float pz = pts[p * 3 + 2];

    const int G = 32 >> s;
    int cellBase;
    switch (s) { case 0: cellBase = 0; break; case 1: cellBase = 32768; break;
                 case 2: cellBase = 36864; break; default: cellBase = 37376; }

    const float ve  = __fmul_rn(0.015f, (float)(2 << s));
    const float inv = 1.0f / ve;

    int cx = (int)((px + 0.48f) * inv); cx = min(max(cx, 0), G - 1);
    int cy = (int)((py + 0.48f) * inv); cy = min(max(cy, 0), G - 1);
    int cz = (int)((pz + 0.48f) * inv); cz = min(max(cz, 0), G - 1);

    float b0 = 3.0e38f, b1 = 3.0e38f, b2 = 3.0e38f;
    int   n0 = 0x7fffffff, n1 = 0x7fffffff, n2 = 0x7fffffff;

    for (int r = 1; r <= G; r++) {
        int lox = max(cx - r, 0), hix = min(cx + r, G - 1);
        int loy = max(cy - r, 0), hiy = min(cy + r, G - 1);
        int loz = max(cz - r, 0), hiz = min(cz + r, G - 1);
        for (int x = lox; x <= hix; x++) {
            int ax = x > cx ? x - cx : cx - x;
            for (int y = loy; y <= hiy; y++) {
                int ay = y > cy ? y - cy : cy - y;
                for (int z = loz; z <= hiz; z++) {
                    int az = z > cz ? z - cz : cz - z;
                    // shell-only for r>1 (cube radius r-1 already scanned)
                    if (r > 1 && ax < r && ay < r && az < r) continue;
                    int cell = cellBase + (x * G + y) * G + z;
                    int cnt  = min(g_cnt[cell], CAP);
                    int base = cell * CAP;
                    for (int j = 0; j < cnt; j++) {
                        float4 q = g_bctr[base + j];
                        int    m = g_bidx[base + j];
                        float dx = __fsub_rn(px, q.x);
                        float dy = __fsub_rn(py, q.y);
                        float dz = __fsub_rn(pz, q.z);
                        float d  = __fadd_rn(__fadd_rn(__fmul_rn(dx, dx),
                                                       __fmul_rn(dy, dy)),
                                             __fmul_rn(dz, dz));
                        // lexicographic (d, index) insert: order-independent,
                        // reproduces top_k's lower-index tie-break exactly.
                        if (d < b2 || (d == b2 && m < n2)) {
                            if (d < b1 || (d == b1 && m < n1)) {
                                b2 = b1; n2 = n1;
                                if (d < b0 || (d == b0 && m < n0)) {
                                    b1 = b0; n1 = n0; b0 = d; n0 = m;
                                } else { b1 = d; n1 = m; }
                            } else { b2 = d; n2 = m; }
                        }
                    }
                }
            }
        }
        // any unscanned center has axis distance >= (r+0.5)*ve; 0.998 margin
        // makes the fp32 bound strictly conservative.
        float tb = __fmul_rn(__fadd_rn((float)r, 0.5f), ve);
        float bq = __fmul_rn(__fmul_rn(tb, tb), 0.998f);
        if (n2 != 0x7fffffff && b2 < bq) break;
    }

    // weights — identical op order to the previously passing kernel
    float r0 = __fdiv_rn(1.0f, __fadd_rn(b0, 1e-8f));
    float r1 = __fdiv_rn(1.0f, __fadd_rn(b1, 1e-8f));
    float r2 = __fdiv_rn(1.0f, __fadd_rn(b2, 1e-8f));
    float sm = __fadd_rn(__fadd_rn(r0, r1), r2);

    __shared__ float sw[32][4][3];
    __shared__ int   sn[32][4][3];
    sw[lp][s][0] = __fdiv_rn(r0, sm);
    sw[lp][s][1] = __fdiv_rn(r1, sm);
    sw[lp][s][2] = __fdiv_rn(r2, sm);
    sn[lp][s][0] = n0; sn[lp][s][1] = n1; sn[lp][s][2] = n2;
    __syncthreads();

    // fused gather: 32 points x 480 channels, cooperative across the CTA
    for (int e = threadIdx.x; e < 32 * OUT_STRIDE; e += 128) {
        int pp = e / OUT_STRIDE;
        int c  = e - pp * OUT_STRIDE;
        int ss, lc, C; const float* f;
        if (c < 32)       { ss = 0; lc = c;       C = 32;  f = f1; }
        else if (c < 96)  { ss = 1; lc = c - 32;  C = 64;  f = f2; }
        else if (c < 224) { ss = 2; lc = c - 96;  C = 128; f = f3; }
        else              { ss = 3; lc = c - 224; C = 256; f = f4; }
        int   j0 = sn[pp][ss][0], j1 = sn[pp][ss][1], j2 = sn[pp][ss][2];
        float w0 = sw[pp][ss][0], w1 = sw[pp][ss][1], w2 = sw[pp][ss][2];
        float v = w0 * f[j0 * C + lc];
        v = fmaf(w1, f[j1 * C + lc], v);
        v = fmaf(w2, f[j2 * C + lc], v);
        out[(blockIdx.x * 32 + pp) * OUT_STRIDE + c] = v;
    }
}

// ---------------------------------------------------------------------------
extern "C" void kernel_launch(void* const* d_in, const int* in_sizes, int n_in,
                              void* d_out, int out_size)
{
    // identify inputs by (distinct) element counts — order-proof
    const float* points   = nullptr;
    const int*   idx[4]   = {nullptr, nullptr, nullptr, nullptr};
    const float* feats[4] = {nullptr, nullptr, nullptr, nullptr};

    for (int i = 0; i < n_in; i++) {
        switch (in_sizes[i]) {
            case 24576:  points   = (const float*)d_in[i]; break; // points [8192,3]
            case 64000:  idx[0]   = (const int*)  d_in[i]; break; // indices1 [16000,4]
            case 512000: feats[0] = (const float*)d_in[i]; break; // feats1 [16000,32]
            case 16000:  idx[1]   = (const int*)  d_in[i]; break; // indices2 [4000,4]
            case 256000: feats[1] = (const float*)d_in[i]; break; // feats2 [4000,64]
            case 2048:   idx[2]   = (const int*)  d_in[i]; break; // indices3 [512,4]
            case 65536:  feats[2] = (const float*)d_in[i]; break; // feats3 [512,128]
            case 256:    idx[3]   = (const int*)  d_in[i]; break; // indices4 [64,4]
            case 16384:  feats[3] = (const float*)d_in[i]; break; // feats4 [64,256]
            default: break;                                       // batch_ids unused
        }
    }

    k_zero<<<(NCELLS + 255) / 256, 256>>>();
    k_scatter<<<(20576 + 255) / 256, 256>>>(idx[0], idx[1], idx[2], idx[3]);
    k_query<<<N_POINTS / 32, 128>>>(points, feats[0], feats[1], feats[2], feats[3],
                                    (float*)d_out);
}

// round 6
// speedup vs baseline: 6.3014x; 1.5621x over previous
#include <cuda_runtime.h>

// ----------------------------------------------------------------------------
// Ops_GetPointFeat_spconv: multi-scale 3-NN inverse-distance interpolation,
// grid-bucketed, 8-lane-per-task parallel ring search.
//
// Selection = min over 64-bit keys (float_bits(d2)<<32 | index): exactly
// lexicographic (d2, index)  ==  jax.lax.top_k tie-break (lower index wins),
// independent of scan/scatter order. d2 uses the reference's RN op order.
//
// R5 fix: shuffle masks are segment-local (8 lanes). Groups in the same warp
// exit the ring loop at different radii; a full-warp mask deadlocks.
// ----------------------------------------------------------------------------

#define N_POINTS   8192
#define OUT_STRIDE 480
#define CAP        32
#define NCELLS     37440   // 32^3 + 16^3 + 8^3 + 4^3
#define KINF       0xFFFFFFFFFFFFFFFFULL

static __device__ int    g_cnt[NCELLS];
static __device__ float4 g_bctr[CAP * NCELLS];  // slot-major: [j][cell]
static __device__ int    g_bidx[CAP * NCELLS];  // slot-major: [j][cell]

// ---------------------------------------------------------------------------
__global__ void k_zero()
{
    int i = blockIdx.x * 256 + threadIdx.x;
    if (i < NCELLS) g_cnt[i] = 0;
}

// ---------------------------------------------------------------------------
__global__ void k_scatter(const int* __restrict__ i1, const int* __restrict__ i2,
                          const int* __restrict__ i3, const int* __restrict__ i4)
{
    int t = blockIdx.x * 256 + threadIdx.x;
    if (t >= 20576) return;

    int s, local, G, cellBase; const int* idx;
    if (t < 16000)      { s = 0; local = t;         G = 32; cellBase = 0;     idx = i1; }
    else if (t < 20000) { s = 1; local = t - 16000; G = 16; cellBase = 32768; idx = i2; }
    else if (t < 20512) { s = 2; local = t - 20000; G = 8;  cellBase = 36864; idx = i3; }
    else                { s = 3; local = t - 20512; G = 4;  cellBase = 37376; idx = i4; }

    int ix = idx[local * 4 + 1];
    int iy = idx[local * 4 + 2];
    int iz = idx[local * 4 + 3];

    float sf   = (float)(2 << s);
    float ve   = __fmul_rn(0.015f, sf);
    float off  = __fmul_rn(__fmul_rn(-0.5f, 0.015f), 64.0f);  // -0.48
    float half = __fmul_rn(0.5f, ve);

    float4 c;
    c.x = __fadd_rn(__fadd_rn(__fmul_rn((float)ix, ve), off), half);
    c.y = __fadd_rn(__fadd_rn(__fmul_rn((float)iy, ve), off), half);
    c.z = __fadd_rn(__fadd_rn(__fmul_rn((float)iz, ve), off), half);
    c.w = 0.0f;

    int cell = cellBase + (ix * G + iy) * G + iz;
    int pos  = atomicAdd(&g_cnt[cell], 1);
    if (pos < CAP) {
        g_bctr[pos * NCELLS + cell] = c;
        g_bidx[pos * NCELLS + cell] = local;
    }
}

// ---------------------------------------------------------------------------
// Query: 32768 tasks (point x scale), 8 lanes per task, 16 tasks per CTA.
// CTA is single-scale (blockIdx>>9 = scale). Shell cells distributed over the
// 8 lanes round-robin; per-ring top-3 merge via segment-masked shuffles.
// ---------------------------------------------------------------------------
__global__ void __launch_bounds__(128)
k_query(const float* __restrict__ pts,
        const float* __restrict__ f1, const float* __restrict__ f2,
        const float* __restrict__ f3, const float* __restrict__ f4,
        float* __restrict__ out)
{
    const int lane8 = threadIdx.x & 7;
    const int group = threadIdx.x >> 3;              // 0..15
    const int gid   = blockIdx.x * 16 + group;       // 0..32767
    const int s     = gid >> 13;                     // scale (uniform per CTA)
    const int p     = gid & (N_POINTS - 1);

    // mask naming ONLY this 8-lane segment of the warp (deadlock fix)
    const unsigned gmask = 0xFFu << (((threadIdx.x >> 3) & 3) * 8);

    const float px = pts[p * 3 + 0];
    const float py = pts[p * 3 + 1];
    const float pz = pts[p * 3 + 2];

    const int G = 32 >> s;
    int cellBase;
    switch (s) { case 0: cellBase = 0; break; case 1: cellBase = 32768; break;
                 case 2: cellBase = 36864; break; default: cellBase = 37376; }

    const float ve  = __fmul_rn(0.015f, (float)(2 << s));
    const float inv = 1.0f / ve;

    int cx = (int)((px + 0.48f) * inv); cx = min(max(cx, 0), G - 1);
    int cy = (int)((py + 0.48f) * inv); cy = min(max(cy, 0), G - 1);
    int cz = (int)((pz + 0.48f) * inv); cz = min(max(cz, 0), G - 1);

    unsigned long long k0 = KINF, k1 = KINF, k2 = KINF;   // per-lane top-3
    unsigned long long m0 = KINF, m1 = KINF, m2 = KINF;   // group-merged top-3

    for (int r = 1; r <= G; r++) {
        int lox = max(cx - r, 0), hix = min(cx + r, G - 1);
        int loy = max(cy - r, 0), hiy = min(cy + r, G - 1);
        int loz = max(cz - r, 0), hiz = min(cz + r, G - 1);
        int en = 0;  // enumeration counter (identical on all 8 lanes)
        for (int x = lox; x <= hix; x++) {
            int ax = x > cx ? x - cx : cx - x;
            for (int y = loy; y <= hiy; y++) {
                int ay = y > cy ? y - cy : cy - y;
                int rowBase = cellBase + (x * G + y) * G;
                for (int z = loz; z <= hiz; z++) {
                    int az = z > cz ? z - cz : cz - z;
                    if (r > 1 && ax < r && ay < r && az < r) continue; // shell only
                    if ((en++ & 7) != lane8) continue;

                    int cell = rowBase + z;
                    // issue cnt + slot0 loads together (independent addrs)
                    int    cnt = __ldg(&g_cnt[cell]);
                    float4 q   = __ldg(&g_bctr[cell]);       // slot 0
                    int    mi  = __ldg(&g_bidx[cell]);       // slot 0
                    cnt = min(cnt, CAP);
                    for (int j = 0; j < cnt; j++) {
                        if (j > 0) {
                            q  = __ldg(&g_bctr[j * NCELLS + cell]);
                            mi = __ldg(&g_bidx[j * NCELLS + cell]);
                        }
                        float dx = __fsub_rn(px, q.x);
                        float dy = __fsub_rn(py, q.y);
                        float dz = __fsub_rn(pz, q.z);
                        float d  = __fadd_rn(__fadd_rn(__fmul_rn(dx, dx),
                                                       __fmul_rn(dy, dy)),
                                             __fmul_rn(dz, dz));
                        unsigned long long key =
                            ((unsigned long long)__float_as_uint(d) << 32) |
                            (unsigned)mi;
                        if (key < k2) {
                            if (key < k1) {
                                k2 = k1;
                                if (key < k0) { k1 = k0; k0 = key; }
                                else          { k1 = key; }
                            } else { k2 = key; }
                        }
                    }
                }
            }
        }

        // merge top-3 across the 8-lane group (destructive on copies).
        // Break condition below is uniform within the segment, so the segment
        // is convergent at every shuffle.
        unsigned long long c0 = k0, c1 = k1, c2 = k2;
        #pragma unroll
        for (int round = 0; round < 3; round++) {
            unsigned long long v = c0;
            #pragma unroll
            for (int off = 4; off > 0; off >>= 1) {
                unsigned long long o = __shfl_xor_sync(gmask, v, off, 8);
                v = v < o ? v : o;
            }
            if (c0 == v) { c0 = c1; c1 = c2; c2 = KINF; }  // unique keys: 1 pop
            if (round == 0) m0 = v; else if (round == 1) m1 = v; else m2 = v;
        }

        // conservative stop: unscanned centers are >= (r+0.5)*ve away per axis
        float tb = __fmul_rn(__fadd_rn((float)r, 0.5f), ve);
        float bq = __fmul_rn(__fmul_rn(tb, tb), 0.998f);
        if (m2 != KINF && __uint_as_float((unsigned)(m2 >> 32)) < bq) break;
    }

    // weights — identical RN op order to the passing kernel
    float b0 = __uint_as_float((unsigned)(m0 >> 32));
    float b1 = __uint_as_float((unsigned)(m1 >> 32));
    float b2 = __uint_as_float((unsigned)(m2 >> 32));
    float r0 = __fdiv_rn(1.0f, __fadd_rn(b0, 1e-8f));
    float r1 = __fdiv_rn(1.0f, __fadd_rn(b1, 1e-8f));
    float r2 = __fdiv_rn(1.0f, __fadd_rn(b2, 1e-8f));
    float sm = __fadd_rn(__fadd_rn(r0, r1), r2);

    __shared__ float sw[16][3];
    __shared__ int   sn[16][3];
    if (lane8 == 0) {
        sw[group][0] = __fdiv_rn(r0, sm);
        sw[group][1] = __fdiv_rn(r1, sm);
        sw[group][2] = __fdiv_rn(r2, sm);
        sn[group][0] = (int)(unsigned)(m0 & 0xFFFFFFFFu);
        sn[group][1] = (int)(unsigned)(m1 & 0xFFFFFFFFu);
        sn[group][2] = (int)(unsigned)(m2 & 0xFFFFFFFFu);
    }
    __syncthreads();

    // gather: this CTA's 16 points, single scale slice of the output
    int C, oOff, csh; const float* f;
    switch (s) {
        case 0:  C = 32;  oOff = 0;   csh = 5; f = f1; break;
        case 1:  C = 64;  oOff = 32;  csh = 6; f = f2; break;
        case 2:  C = 128; oOff = 96;  csh = 7; f = f3; break;
        default: C = 256; oOff = 224; csh = 8; f = f4; break;
    }
    const int pBase = (blockIdx.x & 511) * 16;
    for (int e = threadIdx.x; e < (16 << csh); e += 128) {
        int pp = e >> csh;
        int c  = e & (C - 1);
        int   j0 = sn[pp][0], j1 = sn[pp][1], j2 = sn[pp][2];
        float w0 = sw[pp][0], w1 = sw[pp][1], w2 = sw[pp][2];
        float v = w0 * f[j0 * C + c];
        v = fmaf(w1, f[j1 * C + c], v);
        v = fmaf(w2, f[j2 * C + c], v);
        out[(pBase + pp) * OUT_STRIDE + oOff + c] = v;
    }
}

// ---------------------------------------------------------------------------
extern "C" void kernel_launch(void* const* d_in, const int* in_sizes, int n_in,
                              void* d_out, int out_size)
{
    const float* points   = nullptr;
    const int*   idx[4]   = {nullptr, nullptr, nullptr, nullptr};
    const float* feats[4] = {nullptr, nullptr, nullptr, nullptr};

    for (int i = 0; i < n_in; i++) {
        switch (in_sizes[i]) {
            case 24576:  points   = (const float*)d_in[i]; break; // points [8192,3]
            case 64000:  idx[0]   = (const int*)  d_in[i]; break; // indices1
            case 512000: feats[0] = (const float*)d_in[i]; break; // feats1
            case 16000:  idx[1]   = (const int*)  d_in[i]; break; // indices2
            case 256000: feats[1] = (const float*)d_in[i]; break; // feats2
            case 2048:   idx[2]   = (const int*)  d_in[i]; break; // indices3
            case 65536:  feats[2] = (const float*)d_in[i]; break; // feats3
            case 256:    idx[3]   = (const int*)  d_in[i]; break; // indices4
            case 16384:  feats[3] = (const float*)d_in[i]; break; // feats4
            default: break;                                       // batch_ids unused
        }
    }

    k_zero<<<(NCELLS + 255) / 256, 256>>>();
    k_scatter<<<(20576 + 255) / 256, 256>>>(idx[0], idx[1], idx[2], idx[3]);
    k_query<<<2048, 128>>>(points, feats[0], feats[1], feats[2], feats[3],
                           (float*)d_out);
}

// round 9
// speedup vs baseline: 8.2907x; 1.3157x over previous
#include <cuda_runtime.h>

// ----------------------------------------------------------------------------
// Ops_GetPointFeat_spconv: multi-scale 3-NN inverse-distance interpolation.
// Grid-bucketed; ONE WARP per (point, scale) task — warp-uniform ring search,
// REDUX-based top-3 merge, fused per-warp feature gather.
//
// Selection = min over 64-bit keys (float_bits(d2)<<32 | index): exactly
// lexicographic (d2, index)  ==  jax.lax.top_k tie-break (lower index wins),
// independent of scan/scatter order. d2 uses the reference's RN op order.
// ----------------------------------------------------------------------------

#define N_POINTS   8192
#define OUT_STRIDE 480
#define CAP        32
#define NCELLS     37440   // 32^3 + 16^3 + 8^3 + 4^3
#define KINF       0xFFFFFFFFFFFFFFFFULL
#define FULL       0xFFFFFFFFu

static __device__ int    g_cnt[NCELLS];
static __device__ float4 g_bctr[CAP * NCELLS];  // slot-major: [j][cell]
static __device__ int    g_bidx[CAP * NCELLS];  // slot-major: [j][cell]

// ---------------------------------------------------------------------------
__global__ void k_zero()
{
    int i = blockIdx.x * 256 + threadIdx.x;
    if (i < NCELLS) g_cnt[i] = 0;
}

// ---------------------------------------------------------------------------
__global__ void k_scatter(const int* __restrict__ i1, const int* __restrict__ i2,
                          const int* __restrict__ i3, const int* __restrict__ i4)
{
    int t = blockIdx.x * 256 + threadIdx.x;
    if (t >= 20576) return;

    int s, local, G, cellBase; const int* idx;
    if (t < 16000)      { s = 0; local = t;         G = 32; cellBase = 0;     idx = i1; }
    else if (t < 20000) { s = 1; local = t - 16000; G = 16; cellBase = 32768; idx = i2; }
    else if (t < 20512) { s = 2; local = t - 20000; G = 8;  cellBase = 36864; idx = i3; }
    else                { s = 3; local = t - 20512; G = 4;  cellBase = 37376; idx = i4; }

    int ix = idx[local * 4 + 1];
    int iy = idx[local * 4 + 2];
    int iz = idx[local * 4 + 3];

    float sf   = (float)(2 << s);
    float ve   = __fmul_rn(0.015f, sf);
    float off  = __fmul_rn(__fmul_rn(-0.5f, 0.015f), 64.0f);  // -0.48
    float half = __fmul_rn(0.5f, ve);

    float4 c;
    c.x = __fadd_rn(__fadd_rn(__fmul_rn((float)ix, ve), off), half);
    c.y = __fadd_rn(__fadd_rn(__fmul_rn((float)iy, ve), off), half);
    c.z = __fadd_rn(__fadd_rn(__fmul_rn((float)iz, ve), off), half);
    c.w = 0.0f;

    int cell = cellBase + (ix * G + iy) * G + iz;
    int pos  = atomicAdd(&g_cnt[cell], 1);
    if (pos < CAP) {
        g_bctr[pos * NCELLS + cell] = c;
        g_bidx[pos * NCELLS + cell] = local;
    }
}

// ---------------------------------------------------------------------------
// Query: one warp per (point, scale). 32768 warps = 4096 CTAs x 8 warps.
// Ring r=1: direct lane->cell map over the 3^3 cube (single pass).
// Ring r>=2: shell cells distributed round-robin over 32 lanes.
// Top-3 merge: 3 rounds of (REDUX d2-min, REDUX index-min among matching).
// Everything warp-uniform -> no divergence between tasks, full-mask safe.
// ---------------------------------------------------------------------------
__global__ void __launch_bounds__(256)
k_query(const float* __restrict__ pts,
        const float* __restrict__ f1, const float* __restrict__ f2,
        const float* __restrict__ f3, const float* __restrict__ f4,
        float* __restrict__ out)
{
    const int lane = threadIdx.x & 31;
    const int gid  = blockIdx.x * 8 + (threadIdx.x >> 5);  // 0..32767
    const int s    = gid >> 13;                            // scale (warp-uniform)
    const int p    = gid & (N_POINTS - 1);

    const float px = __ldg(&pts[p * 3 + 0]);
    const float py = __ldg(&pts[p * 3 + 1]);
    const float pz = __ldg(&pts[p * 3 + 2]);

    const int G = 32 >> s;
    int cellBase;
    switch (s) { case 0: cellBase = 0; break; case 1: cellBase = 32768; break;
                 case 2: cellBase = 36864; break; default: cellBase = 37376; }

    const float ve  = __fmul_rn(0.015f, (float)(2 << s));
    const float inv = 1.0f / ve;

    int cx = (int)((px + 0.48f) * inv); cx = min(max(cx, 0), G - 1);
    int cy = (int)((py + 0.48f) * inv); cy = min(max(cy, 0), G - 1);
    int cz = (int)((pz + 0.48f) * inv); cz = min(max(cz, 0), G - 1);

    unsigned long long k0 = KINF, k1 = KINF, k2 = KINF;   // per-lane sorted top-3
    unsigned long long m0 = KINF, m1 = KINF, m2 = KINF;   // warp-merged top-3

    for (int r = 1; r <= G; r++) {
        if (r == 1) {
            // direct map: lane l < 27 -> cube cell (dx,dy,dz) in [-1,1]^3
            if (lane < 27) {
                int x = cx + lane / 9 - 1;
                int y = cy + (lane / 3) % 3 - 1;
                int z = cz + lane % 3 - 1;
                if (x >= 0 && x < G && y >= 0 && y < G && z >= 0 && z < G) {
                    int cell = cellBase + (x * G + y) * G + z;
                    int    cnt = __ldg(&g_cnt[cell]);
                    float4 q   = __ldg(&g_bctr[cell]);
                    int    mi  = __ldg(&g_bidx[cell]);
                    cnt = min(cnt, CAP);
                    for (int j = 0; j < cnt; j++) {
                        if (j > 0) {
                            q  = __ldg(&g_bctr[j * NCELLS + cell]);
                            mi = __ldg(&g_bidx[j * NCELLS + cell]);
                        }
                        float dx = __fsub_rn(px, q.x);
                        float dy = __fsub_rn(py, q.y);
                        float dz = __fsub_rn(pz, q.z);
                        float d  = __fadd_rn(__fadd_rn(__fmul_rn(dx, dx),
                                                       __fmul_rn(dy, dy)),
                                             __fmul_rn(dz, dz));
                        unsigned long long key =
                            ((unsigned long long)__float_as_uint(d) << 32) |
                            (unsigned)mi;
                        if (key < k2) {
                            if (key < k1) {
                                k2 = k1;
                                if (key < k0) { k1 = k0; k0 = key; }
                                else          { k1 = key; }
                            } else { k2 = key; }
                        }
                    }
                }
            }
        } else {
            int lox = max(cx - r, 0), hix = min(cx + r, G - 1);
            int loy = max(cy - r, 0), hiy = min(cy + r, G - 1);
            int loz = max(cz - r, 0), hiz = min(cz + r, G - 1);
            int en = 0;  // identical on all lanes
            for (int x = lox; x <= hix; x++) {
                int ax = x > cx ? x - cx : cx - x;
                for (int y = loy; y <= hiy; y++) {
                    int ay = y > cy ? y - cy : cy - y;
                    int rowBase = cellBase + (x * G + y) * G;
                    for (int z = loz; z <= hiz; z++) {
                        int az = z > cz ? z - cz : cz - z;
                        if (ax < r && ay < r && az < r) continue;  // shell only
                        if ((en++ & 31) != lane) continue;

                        int cell = rowBase + z;
                        int    cnt = __ldg(&g_cnt[cell]);
                        float4 q   = __ldg(&g_bctr[cell]);
                        int    mi  = __ldg(&g_bidx[cell]);
                        cnt = min(cnt, CAP);
                        for (int j = 0; j < cnt; j++) {
                            if (j > 0) {
                                q  = __ldg(&g_bctr[j * NCELLS + cell]);
                                mi = __ldg(&g_bidx[j * NCELLS + cell]);
                            }
                            float dx = __fsub_rn(px, q.x);
                            float dy = __fsub_rn(py, q.y);
                            float dz = __fsub_rn(pz, q.z);
                            float d  = __fadd_rn(__fadd_rn(__fmul_rn(dx, dx),
                                                           __fmul_rn(dy, dy)),
                                                 __fmul_rn(dz, dz));
                            unsigned long long key =
                                ((unsigned long long)__float_as_uint(d) << 32) |
                                (unsigned)mi;
                            if (key < k2) {
                                if (key < k1) {
                                    k2 = k1;
                                    if (key < k0) { k1 = k0; k0 = key; }
                                    else          { k1 = key; }
                                } else { k2 = key; }
                            }
                        }
                    }
                }
            }
        }

        // warp-wide top-3 merge on copies (lane-local lists stay intact).
        // Each lane's list is sorted, so the global i-th min is some lane's
        // current head -> 3 rounds of (d2 min, index min among d2 matches).
        unsigned long long c0 = k0, c1 = k1, c2 = k2;
        #pragma unroll
        for (int round = 0; round < 3; round++) {
            unsigned hd   = (unsigned)(c0 >> 32);
            unsigned dmin = __reduce_min_sync(FULL, hd);
            unsigned isel = (hd == dmin) ? (unsigned)c0 : 0xFFFFFFFFu;
            unsigned imin = __reduce_min_sync(FULL, isel);
            unsigned long long m = ((unsigned long long)dmin << 32) | imin;
            if (c0 == m) { c0 = c1; c1 = c2; c2 = KINF; }  // unique keys
            if (round == 0) m0 = m; else if (round == 1) m1 = m; else m2 = m;
        }

        // conservative stop: unscanned centers >= (r+0.5)*ve away per axis
        float tb = __fmul_rn(__fadd_rn((float)r, 0.5f), ve);
        float bq = __fmul_rn(__fmul_rn(tb, tb), 0.998f);
        if (m2 != KINF && __uint_as_float((unsigned)(m2 >> 32)) < bq) break;
    }

    // weights — identical RN op order to the passing kernel (all lanes)
    float b0 = __uint_as_float((unsigned)(m0 >> 32));
    float b1 = __uint_as_float((unsigned)(m1 >> 32));
    float b2 = __uint_as_float((unsigned)(m2 >> 32));
    float r0 = __fdiv_rn(1.0f, __fadd_rn(b0, 1e-8f));
    float r1 = __fdiv_rn(1.0f, __fadd_rn(b1, 1e-8f));
    float r2 = __fdiv_rn(1.0f, __fadd_rn(b2, 1e-8f));
    float sm = __fadd_rn(__fadd_rn(r0, r1), r2);
    float w0 = __fdiv_rn(r0, sm);
    float w1 = __fdiv_rn(r1, sm);
    float w2 = __fdiv_rn(r2, sm);
    int   j0 = (int)(unsigned)(m0 & 0xFFFFFFFFu);
    int   j1 = (int)(unsigned)(m1 & 0xFFFFFFFFu);
    int   j2 = (int)(unsigned)(m2 & 0xFFFFFFFFu);

    // fused per-warp gather: C channels of this point's scale slice
    int C, oOff; const float* f;
    switch (s) {
        case 0:  C = 32;  oOff = 0;   f = f1; break;
        case 1:  C = 64;  oOff = 32;  f = f2; break;
        case 2:  C = 128; oOff = 96;  f = f3; break;
        default: C = 256; oOff = 224; f = f4; break;
    }
    float* o = out + p * OUT_STRIDE + oOff;
    for (int c = lane; c < C; c += 32) {
        float v = w0 * __ldg(&f[j0 * C + c]);
        v = fmaf(w1, __ldg(&f[j1 * C + c]), v);
        v = fmaf(w2, __ldg(&f[j2 * C + c]), v);
        o[c] = v;
    }
}

// ---------------------------------------------------------------------------
extern "C" void kernel_launch(void* const* d_in, const int* in_sizes, int n_in,
                              void* d_out, int out_size)
{
    const float* points   = nullptr;
    const int*   idx[4]   = {nullptr, nullptr, nullptr, nullptr};
    const float* feats[4] = {nullptr, nullptr, nullptr, nullptr};

    for (int i = 0; i < n_in; i++) {
        switch (in_sizes[i]) {
            case 24576:  points   = (const float*)d_in[i]; break; // points [8192,3]
            case 64000:  idx[0]   = (const int*)  d_in[i]; break; // indices1
            case 512000: feats[0] = (const float*)d_in[i]; break; // feats1
            case 16000:  idx[1]   = (const int*)  d_in[i]; break; // indices2
            case 256000: feats[1] = (const float*)d_in[i]; break; // feats2
            case 2048:   idx[2]   = (const int*)  d_in[i]; break; // indices3
            case 65536:  feats[2] = (const float*)d_in[i]; break; // feats3
            case 256:    idx[3]   = (const int*)  d_in[i]; break; // indices4
            case 16384:  feats[3] = (const float*)d_in[i]; break; // feats4
            default: break;                                       // batch_ids unused
        }
    }

    k_zero<<<(NCELLS + 255) / 256, 256>>>();
    k_scatter<<<(20576 + 255) / 256, 256>>>(idx[0], idx[1], idx[2], idx[3]);
    k_query<<<4096, 256>>>(points, feats[0], feats[1], feats[2], feats[3],
                           (float*)d_out);
}

// round 12
// speedup vs baseline: 15.6360x; 1.8860x over previous
#include <cuda_runtime.h>

// ----------------------------------------------------------------------------
// Ops_GetPointFeat_spconv: multi-scale 3-NN inverse-distance interpolation.
// Grid-bucketed; ONE WARP per (point, scale); closed-form parallel shell
// enumeration; count-based ring stop; single post-loop REDUX top-3 merge.
//
// Selection = min over 64-bit keys (float_bits(d2)<<32 | index): exactly
// lexicographic (d2, index)  ==  jax.lax.top_k tie-break (lower index wins),
// independent of scan/scatter order. d2 uses the reference's RN op order.
// ----------------------------------------------------------------------------

#define N_POINTS   8192
#define OUT_STRIDE 480
#define CAP        32
#define NCELLS     37440   // 32^3 + 16^3 + 8^3 + 4^3
#define KINF       0xFFFFFFFFFFFFFFFFULL
#define FULL       0xFFFFFFFFu

static __device__ int    g_cnt[NCELLS];
static __device__ float4 g_bctr[CAP * NCELLS];  // slot-major: [j][cell]
static __device__ int    g_bidx[CAP * NCELLS];  // slot-major: [j][cell]

// ---------------------------------------------------------------------------
__global__ void k_zero()
{
    int i = blockIdx.x * 256 + threadIdx.x;
    if (i < NCELLS) g_cnt[i] = 0;
}

// ---------------------------------------------------------------------------
__global__ void k_scatter(const int* __restrict__ i1, const int* __restrict__ i2,
                          const int* __restrict__ i3, const int* __restrict__ i4)
{
    int t = blockIdx.x * 256 + threadIdx.x;
    if (t >= 20576) return;

    int s, local, G, cellBase; const int* idx;
    if (t < 16000)      { s = 0; local = t;         G = 32; cellBase = 0;     idx = i1; }
    else if (t < 20000) { s = 1; local = t - 16000; G = 16; cellBase = 32768; idx = i2; }
    else if (t < 20512) { s = 2; local = t - 20000; G = 8;  cellBase = 36864; idx = i3; }
    else                { s = 3; local = t - 20512; G = 4;  cellBase = 37376; idx = i4; }

    int ix = idx[local * 4 + 1];
    int iy = idx[local * 4 + 2];
    int iz = idx[local * 4 + 3];

    float sf   = (float)(2 << s);
    float ve   = __fmul_rn(0.015f, sf);
    float off  = __fmul_rn(__fmul_rn(-0.5f, 0.015f), 64.0f);  // -0.48
    float half = __fmul_rn(0.5f, ve);

    float4 c;
    c.x = __fadd_rn(__fadd_rn(__fmul_rn((float)ix, ve), off), half);
    c.y = __fadd_rn(__fadd_rn(__fmul_rn((float)iy, ve), off), half);
    c.z = __fadd_rn(__fadd_rn(__fmul_rn((float)iz, ve), off), half);
    c.w = 0.0f;

    int cell = cellBase + (ix * G + iy) * G + iz;
    int pos  = atomicAdd(&g_cnt[cell], 1);
    if (pos < CAP) {
        g_bctr[pos * NCELLS + cell] = c;
        g_bidx[pos * NCELLS + cell] = local;
    }
}

// ---------------------------------------------------------------------------
// Per-lane candidate scan of one cell (inlined helper via macro-free lambda
// style: plain function, compiler inlines).
// ---------------------------------------------------------------------------
__device__ __forceinline__ void scan_cell(int cell, float px, float py, float pz,
                                          unsigned long long& k0,
                                          unsigned long long& k1,
                                          unsigned long long& k2)
{
    int    cnt = __ldg(&g_cnt[cell]);
    float4 q   = __ldg(&g_bctr[cell]);   // slot 0 issued with cnt
    int    mi  = __ldg(&g_bidx[cell]);
    cnt = min(cnt, CAP);
    for (int j = 0; j < cnt; j++) {
        if (j > 0) {
            q  = __ldg(&g_bctr[j * NCELLS + cell]);
            mi = __ldg(&g_bidx[j * NCELLS + cell]);
        }
        float dx = __fsub_rn(px, q.x);
        float dy = __fsub_rn(py, q.y);
        float dz = __fsub_rn(pz, q.z);
        float d  = __fadd_rn(__fadd_rn(__fmul_rn(dx, dx), __fmul_rn(dy, dy)),
                             __fmul_rn(dz, dz));
        unsigned long long key =
            ((unsigned long long)__float_as_uint(d) << 32) | (unsigned)mi;
        if (key < k2) {
            if (key < k1) {
                k2 = k1;
                if (key < k0) { k1 = k0; k0 = key; }
                else          { k1 = key; }
            } else { k2 = key; }
        }
    }
}

// ---------------------------------------------------------------------------
// Query: one warp per (point, scale). 32768 warps = 4096 CTAs x 8 warps.
// r=1: direct lane->cell map (27 cells). r>=2: closed-form decode of the
// unclipped shell (24r^2+2 cells) across lanes, bounds-checked per cell.
// Ring stop: warp count of candidates below bound (== old "3rd best < bq").
// Top-3 merge: once, after the ring loop, via REDUX rounds.
// ---------------------------------------------------------------------------
__global__ void __launch_bounds__(256)
k_query(const float* __restrict__ pts,
        const float* __restrict__ f1, const float* __restrict__ f2,
        const float* __restrict__ f3, const float* __restrict__ f4,
        float* __restrict__ out)
{
    const int lane = threadIdx.x & 31;
    const int gid  = blockIdx.x * 8 + (threadIdx.x >> 5);  // 0..32767
    const int s    = gid >> 13;                            // scale (warp-uniform)
    const int p    = gid & (N_POINTS - 1);

    const float px = __ldg(&pts[p * 3 + 0]);
    const float py = __ldg(&pts[p * 3 + 1]);
    const float pz = __ldg(&pts[p * 3 + 2]);

    const int G = 32 >> s;
    int cellBase;
    switch (s) { case 0: cellBase = 0; break; case 1: cellBase = 32768; break;
                 case 2: cellBase = 36864; break; default: cellBase = 37376; }

    const float ve  = __fmul_rn(0.015f, (float)(2 << s));
    const float inv = 1.0f / ve;

    int cx = (int)((px + 0.48f) * inv); cx = min(max(cx, 0), G - 1);
    int cy = (int)((py + 0.48f) * inv); cy = min(max(cy, 0), G - 1);
    int cz = (int)((pz + 0.48f) * inv); cz = min(max(cz, 0), G - 1);

    unsigned long long k0 = KINF, k1 = KINF, k2 = KINF;   // per-lane sorted top-3

    for (int r = 1; r <= G; r++) {
        if (r == 1) {
            if (lane < 27) {
                int x = cx + lane / 9 - 1;
                int y = cy + (lane / 3) % 3 - 1;
                int z = cz + lane % 3 - 1;
                if (((unsigned)x < (unsigned)G) & ((unsigned)y < (unsigned)G) &
                    ((unsigned)z < (unsigned)G))
                    scan_cell(cellBase + (x * G + y) * G + z, px, py, pz, k0, k1, k2);
            }
        } else {
            // unclipped shell decomposition: 2 x-faces (W^2 each, W=2r+1),
            // 2 y-strips (Wm*W each, Wm=2r-1), 2 z-caps (Wm^2 each).
            const int W  = 2 * r + 1;
            const int Wm = 2 * r - 1;
            const int F  = W * W;
            const int S  = Wm * W;
            const int E  = Wm * Wm;
            const int total = 2 * F + 2 * S + 2 * E;   // 24r^2 + 2
            for (int q = lane; q < total; q += 32) {
                int dx, dy, dz, rem;
                if (q < 2 * F) {                        // x = +-r faces
                    dx = (q < F) ? -r : r;
                    rem = (q < F) ? q : q - F;
                    dy = rem / W - r;
                    dz = rem % W - r;
                } else if (q < 2 * F + 2 * S) {         // y = +-r strips
                    rem = q - 2 * F;
                    dy = (rem < S) ? -r : r;
                    if (rem >= S) rem -= S;
                    dx = rem / W - (r - 1);
                    dz = rem % W - r;
                } else {                                // z = +-r caps
                    rem = q - 2 * F - 2 * S;
                    dz = (rem < E) ? -r : r;
                    if (rem >= E) rem -= E;
                    dx = rem / Wm - (r - 1);
                    dy = rem % Wm - (r - 1);
                }
                int x = cx + dx, y = cy + dy, z = cz + dz;
                if (((unsigned)x < (unsigned)G) & ((unsigned)y < (unsigned)G) &
                    ((unsigned)z < (unsigned)G))
                    scan_cell(cellBase + (x * G + y) * G + z, px, py, pz, k0, k1, k2);
            }
        }

        // stop test: >=3 candidates (warp-wide) strictly below the bound.
        // Per-lane kept-below count is exact-min(3,true) -> warp sum >= 3
        // <=> global 3rd-smallest < bq  (identical decision to merged m2<bq).
        float tb = __fmul_rn(__fadd_rn((float)r, 0.5f), ve);
        float bq = __fmul_rn(__fmul_rn(tb, tb), 0.998f);
        unsigned below =
            (unsigned)(__uint_as_float((unsigned)(k0 >> 32)) < bq) +
            (unsigned)(__uint_as_float((unsigned)(k1 >> 32)) < bq) +
            (unsigned)(__uint_as_float((unsigned)(k2 >> 32)) < bq);
        if (__reduce_add_sync(FULL, below) >= 3) break;
    }

    // final warp-wide lexicographic top-3 merge (lanes' lists are sorted:
    // global i-th min is always some lane's current head).
    unsigned long long m0, m1, m2;
    {
        unsigned long long c0 = k0, c1 = k1, c2 = k2;
        #pragma unroll
        for (int round = 0; round < 3; round++) {
            unsigned hd   = (unsigned)(c0 >> 32);
            unsigned dmin = __reduce_min_sync(FULL, hd);
            unsigned isel = (hd == dmin) ? (unsigned)c0 : 0xFFFFFFFFu;
            unsigned imin = __reduce_min_sync(FULL, isel);
            unsigned long long m = ((unsigned long long)dmin << 32) | imin;
            if (c0 == m) { c0 = c1; c1 = c2; c2 = KINF; }  // unique keys
            if (round == 0) m0 = m; else if (round == 1) m1 = m; else m2 = m;
        }
    }

    // weights — identical RN op order to the passing kernel (all lanes)
    float b0 = __uint_as_float((unsigned)(m0 >> 32));
    float b1 = __uint_as_float((unsigned)(m1 >> 32));
    float b2 = __uint_as_float((unsigned)(m2 >> 32));
    float r0 = __fdiv_rn(1.0f, __fadd_rn(b0, 1e-8f));
    float r1 = __fdiv_rn(1.0f, __fadd_rn(b1, 1e-8f));
    float r2 = __fdiv_rn(1.0f, __fadd_rn(b2, 1e-8f));
    float sm = __fadd_rn(__fadd_rn(r0, r1), r2);
    float w0 = __fdiv_rn(r0, sm);
    float w1 = __fdiv_rn(r1, sm);
    float w2 = __fdiv_rn(r2, sm);
    int   j0 = (int)(unsigned)(m0 & 0xFFFFFFFFu);
    int   j1 = (int)(unsigned)(m1 & 0xFFFFFFFFu);
    int   j2 = (int)(unsigned)(m2 & 0xFFFFFFFFu);

    // fused per-warp gather: C channels of this point's scale slice
    int C, oOff; const float* f;
    switch (s) {
        case 0:  C = 32;  oOff = 0;   f = f1; break;
        case 1:  C = 64;  oOff = 32;  f = f2; break;
        case 2:  C = 128; oOff = 96;  f = f3; break;
        default: C = 256; oOff = 224; f = f4; break;
    }
    float* o = out + p * OUT_STRIDE + oOff;
    for (int c = lane; c < C; c += 32) {
        float v = w0 * __ldg(&f[j0 * C + c]);
        v = fmaf(w1, __ldg(&f[j1 * C + c]), v);
        v = fmaf(w2, __ldg(&f[j2 * C + c]), v);
        o[c] = v;
    }
}

// ---------------------------------------------------------------------------
extern "C" void kernel_launch(void* const* d_in, const int* in_sizes, int n_in,
                              void* d_out, int out_size)
{
    const float* points   = nullptr;
    const int*   idx[4]   = {nullptr, nullptr, nullptr, nullptr};
    const float* feats[4] = {nullptr, nullptr, nullptr, nullptr};

    for (int i = 0; i < n_in; i++) {
        switch (in_sizes[i]) {
            case 24576:  points   = (const float*)d_in[i]; break; // points [8192,3]
            case 64000:  idx[0]   = (const int*)  d_in[i]; break; // indices1
            case 512000: feats[0] = (const float*)d_in[i]; break; // feats1
            case 16000:  idx[1]   = (const int*)  d_in[i]; break; // indices2
            case 256000: feats[1] = (const float*)d_in[i]; break; // feats2
            case 2048:   idx[2]   = (const int*)  d_in[i]; break; // indices3
            case 65536:  feats[2] = (const float*)d_in[i]; break; // feats3
            case 256:    idx[3]   = (const int*)  d_in[i]; break; // indices4
            case 16384:  feats[3] = (const float*)d_in[i]; break; // feats4
            default: break;                                       // batch_ids unused
        }
    }

    k_zero<<<(NCELLS + 255) / 256, 256>>>();
    k_scatter<<<(20576 + 255) / 256, 256>>>(idx[0], idx[1], idx[2], idx[3]);
    k_query<<<4096, 256>>>(points, feats[0], feats[1], feats[2], feats[3],
                           (float*)d_out);
}